// round 14
// baseline (speedup 1.0000x reference)
#include <cuda_runtime.h>

#define NV 256   // vertices
#define KD 16    // degree
#define HD 32    // hidden
#define GRID (NV / 2)

// ---------------- globals ----------------
__device__ float g_F1[NV * 256 * HD];       // layer-1 output, 8 MB
__device__ unsigned g_flag[NV];             // per-vertex publish flag (epoch-stamped)
__device__ unsigned g_epoch;
__device__ unsigned g_done;
__device__ float g_acc;

typedef unsigned long long ull;

__device__ __forceinline__ ull pack2(float x) {
    ull r; asm("mov.b64 %0, {%1, %1};" : "=l"(r) : "f"(x)); return r;
}
__device__ __forceinline__ ull pack2f(float lo, float hi) {
    ull r; asm("mov.b64 %0, {%1, %2};" : "=l"(r) : "f"(lo), "f"(hi)); return r;
}
__device__ __forceinline__ void unpack2(ull v, float& lo, float& hi) {
    asm("mov.b64 {%0, %1}, %2;" : "=f"(lo), "=f"(hi) : "l"(v));
}
__device__ __forceinline__ void dfma(ull& acc, ull a, ull b) {
    asm("fma.rn.f32x2 %0, %1, %2, %0;" : "+l"(acc) : "l"(a), "l"(b));
}
__device__ __forceinline__ ull addx2(ull a, ull b) {
    ull r; asm("add.rn.f32x2 %0, %1, %2;" : "=l"(r) : "l"(a), "l"(b)); return r;
}
__device__ __forceinline__ void gemm_row(ull* y, ull a, const float* wrow) {
    const longlong2* w = (const longlong2*)wrow;
#pragma unroll
    for (int k8 = 0; k8 < 8; k8++) {
        longlong2 v = w[k8];
        dfma(y[2 * k8 + 0], a, (ull)v.x);
        dfma(y[2 * k8 + 1], a, (ull)v.y);
    }
}
__device__ __forceinline__ void cp16(float* sdst, const float4* gsrc) {
    unsigned s = (unsigned)__cvta_generic_to_shared(sdst);
    asm volatile("cp.async.cg.shared.global [%0], [%1], 16;" :: "r"(s), "l"(gsrc));
}

// ---------------- smem layout (floats) ----------------
#define OFF_W    0        // 6144 : shared weights (layer1 [6][512] then layer2 [6][1024])
#define OFF_T0   6144     // 8192 : shared tile0 (per-half layer1 scratch aliases: hv*4096)
#define OFF_T1   14336    // 8192 : shared tile1
#define OFF_PV   22528    // per-vertex region, 6400 floats each, x2
#define PV_SIZE  6400
#define SMEM_FLOATS (OFF_PV + 2 * PV_SIZE)
#define SMEM_BYTES  (SMEM_FLOATS * 4)

// per-vertex offsets (floats within PV)
#define PV_GT   0      // [3][16][36] = 1728
#define PV_DG   1728   // [3][16][36]
#define PV_SAB  3456   // 512
#define PV_STB  3968   // 512
#define PV_SAL  4480   // 32
#define PV_YB   4512   // 1088 = ull[2][272]
#define PV_U    5600   // 512
#define PV_D    6112   // 32
#define PV_RED  6144   // 16
#define PV_INT  6160   // nbr16, qm16, vm16, cnt16, misc4, sM 64w, tbl 8w

// 18-tile shared issue: 2048 float4 over 512 threads
__device__ __forceinline__ void issue_tile18(int w, float* buf, int tid) {
    const float4* src = (const float4*)(g_F1 + (size_t)w * 8192);
#pragma unroll
    for (int k = 0; k < 4; k++) {
        int g = k * 512 + tid;
        int r = g >> 3, c4 = g & 7;
        cp16(buf + r * 32 + ((c4 ^ (r & 7)) << 2), src + g);
    }
    asm volatile("cp.async.commit_group;");
}

__device__ __forceinline__ void acquire_flag(int w, unsigned tgt) {
    const unsigned* fp = &g_flag[w];
    unsigned v;
    do {
        asm volatile("ld.acquire.gpu.global.u32 %0, [%1];" : "=r"(v) : "l"(fp) : "memory");
    } while (v != tgt);
}

__device__ __forceinline__ void collab_pair(const float* gA, const float* dA,
                                            const float* gB, const float* dB,
                                            const float* w0b, const float* w5b,
                                            ull* outA, ull* outB) {
    ull a0 = 0, a1 = 0, b0 = 0, b1 = 0;
#pragma unroll
    for (int c4 = 0; c4 < 8; c4++) {
        float4 ga = *(const float4*)(gA + c4 * 4);
        float4 da = *(const float4*)(dA + c4 * 4);
        float4 gb = *(const float4*)(gB + c4 * 4);
        float4 db = *(const float4*)(dB + c4 * 4);
        float gav[4] = {ga.x, ga.y, ga.z, ga.w};
        float dav[4] = {da.x, da.y, da.z, da.w};
        float gbv[4] = {gb.x, gb.y, gb.z, gb.w};
        float dbv[4] = {db.x, db.y, db.z, db.w};
#pragma unroll
        for (int cl = 0; cl < 4; cl++) {
            int c = c4 * 4 + cl;
            ull w0 = *(const ull*)(w0b + c * 32);
            ull w5 = *(const ull*)(w5b + c * 32);
            dfma(a0, pack2(gav[cl]), w0);
            dfma(b0, pack2(gbv[cl]), w0);
            dfma(a1, pack2(dav[cl]), w5);
            dfma(b1, pack2(dbv[cl]), w5);
        }
    }
    *outA = addx2(a0, a1);
    *outB = addx2(b0, b1);
}

__device__ __forceinline__ void phaseA(int par, int t, const float4* bufv,
                                       float* sGt, float* sDg,
                                       const unsigned* sQM, const signed char* sM,
                                       int aA, int half, int c4A, ull& stbA, ull& stbB) {
    unsigned qm = sQM[t];
    int pA = sM[t * 16 + aA];
    ull acc0 = 0ull, acc1 = 0ull;
    if (pA >= 0) {
        int rbase = pA * 16 + half * 8;
#pragma unroll
        for (int k = 0; k < 8; k++) {
            if (qm & (1u << (half * 8 + k))) {
                int r = rbase + k;
                longlong2 v = *(const longlong2*)(bufv + r * 8 + (c4A ^ (r & 7)));
                acc0 = addx2(acc0, (ull)v.x);
                acc1 = addx2(acc1, (ull)v.y);
            }
        }
    }
    float f0, f1, f2, f3;
    unpack2(acc0, f0, f1);
    unpack2(acc1, f2, f3);
    f0 += __shfl_xor_sync(0xffffffffu, f0, 8);
    f1 += __shfl_xor_sync(0xffffffffu, f1, 8);
    f2 += __shfl_xor_sync(0xffffffffu, f2, 8);
    f3 += __shfl_xor_sync(0xffffffffu, f3, 8);
    stbA = addx2(stbA, pack2f(f0, f1));
    stbB = addx2(stbB, pack2f(f2, f3));
    if (half == 0) {
        float4 o; o.x = f0; o.y = f1; o.z = f2; o.w = f3;
        *(float4*)(sGt + par + aA * 36 + c4A * 4) = o;
    } else {
        longlong2 dv; dv.x = 0; dv.y = 0;
        if (pA >= 0) {
            int rd = pA * 17;
            dv = *(const longlong2*)(bufv + rd * 8 + (c4A ^ (rd & 7)));
        }
        *(longlong2*)(sDg + par + aA * 36 + c4A * 4) = dv;
    }
}

__device__ __forceinline__ void stGather(int t, const float4* bufv, const signed char* sM,
                                         int i, int j, ull* st2) {
    int pa = sM[t * 16 + i], pb = sM[t * 16 + j];
    if ((pa | pb) >= 0) {
        int r = pa * 16 + pb;
#pragma unroll
        for (int c4 = 0; c4 < 8; c4++) {
            longlong2 v = *(const longlong2*)(bufv + r * 8 + (c4 ^ (r & 7)));
            st2[2 * c4 + 0] = addx2(st2[2 * c4 + 0], (ull)v.x);
            st2[2 * c4 + 1] = addx2(st2[2 * c4 + 1], (ull)v.y);
        }
    }
}

__global__ __launch_bounds__(512, 1) void ccn_fused(const int* __restrict__ nbrs,
                                                    const float* __restrict__ X,
                                                    const float* __restrict__ W1,
                                                    const float* __restrict__ b1,
                                                    const float* __restrict__ W2,
                                                    const float* __restrict__ b2,
                                                    const float* __restrict__ fcw,
                                                    const float* __restrict__ fcb,
                                                    float* __restrict__ out) {
    extern __shared__ float smem[];
    float* sW    = smem + OFF_W;
    float* tile0 = smem + OFF_T0;
    float* tile1 = smem + OFF_T1;

    int tid = threadIdx.x;
    int hv  = tid >> 8;          // vertex half
    int lt  = tid & 255;         // local tid within half
    int n   = blockIdx.x * 2 + hv;
    int wBase = blockIdx.x * 2 + NV - 8;   // tile u -> vertex (wBase + u) & 255
    int i = lt >> 4, j = lt & 15;
    int half = (lt >> 3) & 1;
    int c4A = lt & 7;

    float* PV   = smem + OFF_PV + hv * PV_SIZE;
    float* sGt  = PV + PV_GT;
    float* sDg  = PV + PV_DG;
    float* sSAB = PV + PV_SAB;
    float* sSTB = PV + PV_STB;
    float* sSAL = PV + PV_SAL;
    ull*   sYB  = (ull*)(PV + PV_YB);
    float* sU   = PV + PV_U;
    float* sD   = PV + PV_D;
    float* sRED = PV + PV_RED;
    int*      sNbr = (int*)(PV + PV_INT);
    unsigned* sQM  = (unsigned*)(sNbr + 16);
    unsigned* sVM  = (unsigned*)(sQM + 16);
    float*    sCnt = (float*)(sVM + 16);
    unsigned* sMisc = (unsigned*)(sCnt + 16);
    signed char* sM = (signed char*)(sMisc + 4);   // 256 bytes
    signed char* sTbl = sM + 256;                  // 18 bytes

    // per-half layer-1 scratch inside the shared tile0
    float* sc   = tile0 + hv * 4096;
    float* sXn  = sc;
    float* sAB1 = sc + 256;
    float* sTB1 = sc + 512;
    float* sAL1 = sc + 768;
    float* sU1  = sc + 784;
    float* sD1  = sc + 1296;
    float* sB1  = sc + 1328;
    float* sR   = sc + 1360;
    float* sZ   = sc + 1872;

    // ============ stage 0 ============
    {
        int jv = nbrs[n * 16 + i];
        int target = nbrs[n * 16 + j];
        int r = -1;
#pragma unroll
        for (int p = 0; p < 16; p++)
            if (nbrs[jv * 16 + p] == target) r = p;
        sM[lt] = (signed char)r;
        sXn[lt] = X[jv * 16 + j];
    }
    if (lt < 16) sNbr[lt] = nbrs[n * 16 + lt];
    // Wc1 fold (shared): 512 entries, 1 per thread
    {
        int c = tid >> 5, h = tid & 31;
        float s = W1[(0 * 16 + c) * 32 + h];
#pragma unroll
        for (int m = 6; m < 15; m++) s += W1[(m * 16 + c) * 32 + h];
        sW[0 * 512 + c * 32 + h] = 16.0f * s + W1[(5 * 16 + c) * 32 + h];
        sW[1 * 512 + c * 32 + h] = W1[(1 * 16 + c) * 32 + h];
        sW[2 * 512 + c * 32 + h] = 16.0f * W1[(2 * 16 + c) * 32 + h];
        sW[3 * 512 + c * 32 + h] = W1[(3 * 16 + c) * 32 + h];
        sW[4 * 512 + c * 32 + h] = W1[(4 * 16 + c) * 32 + h];
        sW[5 * 512 + c * 32 + h] = W1[(15 * 16 + c) * 32 + h];
    }
    if (lt < HD) sB1[lt] = b1[lt];
    if (lt == 0) sMisc[0] = g_epoch;
    __syncthreads();
    if (lt < 16) {
        unsigned vm = 0, qm = 0;
#pragma unroll
        for (int a = 0; a < 16; a++) {
            int p = sM[lt * 16 + a];
            if (p >= 0) { vm |= 1u << a; qm |= 1u << p; }
        }
        sVM[lt] = vm;
        sQM[lt] = qm;
        sCnt[lt] = (float)__popc(vm);
    }
    if (lt < 18) {   // u -> t table (t = -1 means this half skips tile u)
        int w = (wBase + lt) & 255;
        int t = -1;
#pragma unroll
        for (int p = 0; p < 16; p++)
            if (nbrs[n * 16 + p] == w) t = p;
        sTbl[lt] = (signed char)t;
    }
    __syncthreads();
    unsigned tgt = sMisc[0] + 1;

    // ============ layer 1 (closed forms + row-shared tables) ============
    sAB1[lt] = sCnt[i] * sCnt[i] * sXn[lt];
    {
        float s = 0.0f;
#pragma unroll
        for (int t = 0; t < 16; t++)
            if ((sVM[t] >> i) & 1) s += sCnt[t] * sXn[t * 16 + j];
        sTB1[lt] = s;
    }
#pragma unroll
    for (int rep = 0; rep < 2; rep++) {
        int idx = lt + rep * 256;
        int row = idx >> 5, h = idx & 31;
        float a1 = 0.0f, a2 = 0.0f, zz = 0.0f;
#pragma unroll
        for (int c = 0; c < 16; c++) {
            float xv = sXn[row * 16 + c];
            a1 += xv * sW[0 * 512 + c * 32 + h];
            zz += xv * sW[2 * 512 + c * 32 + h];
            a2 += xv * sW[5 * 512 + c * 32 + h];
        }
        sR[idx] = sCnt[row] * a1 + a2;
        sZ[idx] = zz;
    }
    __syncthreads();
    if (lt < 16) {
        float s = 0.0f;
#pragma unroll
        for (int t = 0; t < 16; t++) s += sAB1[t * 16 + lt];
        sAL1[lt] = s;
    }
    __syncthreads();
    {
        int r0 = lt >> 5, h = lt & 31;
        float ua = 0.0f, ub = 0.0f;
#pragma unroll
        for (int c = 0; c < 16; c++) {
            float w1b = sW[1 * 512 + c * 32 + h];
            float w3b = sW[3 * 512 + c * 32 + h];
            ua += sAB1[r0 * 16 + c] * w1b + sTB1[r0 * 16 + c] * w3b;
            ub += sAB1[(r0 + 8) * 16 + c] * w1b + sTB1[(r0 + 8) * 16 + c] * w3b;
        }
        sU1[r0 * 32 + h] = ua;
        sU1[(r0 + 8) * 32 + h] = ub;
    }
    if (lt < HD) {
        float s = 0.0f;
#pragma unroll
        for (int c = 0; c < 16; c++) s += sAL1[c] * sW[4 * 512 + c * 32 + lt];
        sD1[lt] = s;
    }
    __syncthreads();
    {
        ull y1[16];
#pragma unroll
        for (int k = 0; k < 16; k++) {
            ull u = *(const ull*)(sU1 + i * 32 + 2 * k);
            ull b = *(const ull*)(sB1 + 2 * k);
            y1[k] = addx2(u, b);
            if (i == j) y1[k] = addx2(y1[k], *(const ull*)(sD1 + 2 * k));
        }
        if (sM[i * 16 + j] >= 0) {
            const longlong2* rr = (const longlong2*)(sR + i * 32);
#pragma unroll
            for (int k8 = 0; k8 < 8; k8++) {
                longlong2 v = rr[k8];
                y1[2 * k8 + 0] = addx2(y1[2 * k8 + 0], (ull)v.x);
                y1[2 * k8 + 1] = addx2(y1[2 * k8 + 1], (ull)v.y);
            }
        }
#pragma unroll
        for (int t = 0; t < 16; t++) {
            unsigned vm = sVM[t];
            if (((vm >> i) & (vm >> j)) & 1) {
                const longlong2* zr = (const longlong2*)(sZ + t * 32);
#pragma unroll
                for (int k8 = 0; k8 < 8; k8++) {
                    longlong2 v = zr[k8];
                    y1[2 * k8 + 0] = addx2(y1[2 * k8 + 0], (ull)v.x);
                    y1[2 * k8 + 1] = addx2(y1[2 * k8 + 1], (ull)v.y);
                }
            }
        }
        float* dst = g_F1 + (size_t)(n * 256 + lt) * 32;
#pragma unroll
        for (int q = 0; q < 8; q++) {
            float4 o;
            unpack2(y1[2 * q + 0], o.x, o.y);
            unpack2(y1[2 * q + 1], o.z, o.w);
            o.x = fmaxf(o.x, 0.0f); o.y = fmaxf(o.y, 0.0f);
            o.z = fmaxf(o.z, 0.0f); o.w = fmaxf(o.w, 0.0f);
            ((float4*)dst)[q] = o;
        }
    }
    __threadfence();
    __syncthreads();
    if (lt == 0) atomicExch(&g_flag[n], tgt);   // both halves publish

    // ============ Wc2 fold (shared, 1024 entries over 512 threads) ============
#pragma unroll
    for (int rep = 0; rep < 2; rep++) {
        int idx = tid + rep * 512;
        int c = idx >> 5, h = idx & 31;
        float s = W2[(0 * 32 + c) * 32 + h];
#pragma unroll
        for (int m = 6; m < 15; m++) s += W2[(m * 32 + c) * 32 + h];
        sW[0 * 1024 + c * 32 + h] = 16.0f * s + W2[(5 * 32 + c) * 32 + h];
        sW[1 * 1024 + c * 32 + h] = W2[(1 * 32 + c) * 32 + h];
        sW[2 * 1024 + c * 32 + h] = 16.0f * W2[(2 * 32 + c) * 32 + h];
        sW[3 * 1024 + c * 32 + h] = W2[(3 * 32 + c) * 32 + h];
        sW[4 * 1024 + c * 32 + h] = W2[(4 * 32 + c) * 32 + h];
        sW[5 * 1024 + c * 32 + h] = W2[(15 * 32 + c) * 32 + h];
    }
    __syncthreads();

    // ============ layer 2: 18-tile shared stream ============
    acquire_flag(wBase & 255, tgt);
    issue_tile18(wBase & 255, tile0, tid);

    ull st2[16];
#pragma unroll
    for (int c = 0; c < 16; c++) st2[c] = 0ull;
    ull y[16];
#pragma unroll
    for (int k = 0; k < 16; k++) y[k] = 0ull;
    ull stbA = 0ull, stbB = 0ull;
    int c = 0;
    int tP1 = -1, tP2 = -1;      // t at counters c-1, c-2
    int tColA = -1, tColB = -1;  // rows pending pickup (set at collab time)

    for (int u = 0; u < 18; u++) {
        float* buf = (u & 1) ? tile1 : tile0;
        const float4* bufv = (const float4*)buf;
        asm volatile("cp.async.wait_group 0;");
        __syncthreads();
        if (u < 17) {
            int w = (wBase + u + 1) & 255;
            acquire_flag(w, tgt);
            issue_tile18(w, (u & 1) ? tile0 : tile1, tid);
        }
        int t = sTbl[u];
        if (t >= 0) {
            if (c & 1) {
                if (c >= 3) {
                    if (i == tColA) {
#pragma unroll
                        for (int k = 0; k < 16; k++) y[k] = addx2(y[k], sYB[j * 17 + k]);
                    }
                    if (i == tColB) {
#pragma unroll
                        for (int k = 0; k < 16; k++) y[k] = addx2(y[k], sYB[272 + j * 17 + k]);
                    }
                }
            } else if (c >= 2) {
                int sA = ((c - 1) % 3) * 576, sB = ((c - 2) % 3) * 576;
                collab_pair(sGt + sA + i * 36, sDg + sA + i * 36,
                            sGt + sB + i * 36, sDg + sB + i * 36,
                            sW + 2 * j, sW + 5 * 1024 + 2 * j,
                            &sYB[i * 17 + j], &sYB[272 + i * 17 + j]);
                tColA = tP1;   // tile at counter c-1
                tColB = tP2;   // tile at counter c-2
            }
            phaseA((c % 3) * 576, t, bufv, sGt, sDg, sQM, sM, i, half, c4A, stbA, stbB);
            stGather(t, bufv, sM, i, j, st2);
            if (c >= 1 && lt < 32) {
                const float* gp = sGt + ((c - 1) % 3) * 576;
                float s = 0.0f;
#pragma unroll
                for (int a = 0; a < 16; a++) s += gp[a * 36 + lt];
                sSAB[tP1 * 32 + lt] = s;      // row = actual neighbor index
            }
            tP2 = tP1;
            tP1 = t;
            c++;
        }
    }

    // ============ epilogue (per half; c == 16; last tiles at counters 15/14 = tP1/tP2) ============
    __syncthreads();                           // E1: last phaseA visible
    collab_pair(sGt + 0 * 576 + i * 36, sDg + 0 * 576 + i * 36,    // counter 15 (slot 0)
                sGt + 2 * 576 + i * 36, sDg + 2 * 576 + i * 36,    // counter 14 (slot 2)
                sW + 2 * j, sW + 5 * 1024 + 2 * j,
                &sYB[i * 17 + j], &sYB[272 + i * 17 + j]);
    if (lt < 32) {                             // sum_ab of counter-15 tile (slot 0), row tP1
        const float* gp = sGt + 0 * 576;
        float s = 0.0f;
#pragma unroll
        for (int a = 0; a < 16; a++) s += gp[a * 36 + lt];
        sSAB[tP1 * 32 + lt] = s;
    }
    if (half == 0) {
        float4 o;
        unpack2(stbA, o.x, o.y);
        unpack2(stbB, o.z, o.w);
        *(float4*)(sSTB + i * 32 + c4A * 4) = o;
    }
    __syncthreads();                           // E2
    if (i == tP1) {
#pragma unroll
        for (int k = 0; k < 16; k++) y[k] = addx2(y[k], sYB[j * 17 + k]);
    }
    if (i == tP2) {
#pragma unroll
        for (int k = 0; k < 16; k++) y[k] = addx2(y[k], sYB[272 + j * 17 + k]);
    }
    if (lt < 32) {
        float s = 0.0f;
#pragma unroll
        for (int t = 0; t < 16; t++) s += sSAB[t * 32 + lt];
        sSAL[lt] = s;
    }
    __syncthreads();                           // E3
    {
        int r0 = lt >> 5, h = lt & 31;
        float ua = 0.0f, ub = 0.0f;
#pragma unroll
        for (int cc = 0; cc < 32; cc++) {
            float w1b = sW[1 * 1024 + cc * 32 + h];
            float w3b = sW[3 * 1024 + cc * 32 + h];
            ua += sSAB[r0 * 32 + cc] * w1b + sSTB[r0 * 32 + cc] * w3b;
            ub += sSAB[(r0 + 8) * 32 + cc] * w1b + sSTB[(r0 + 8) * 32 + cc] * w3b;
        }
        sU[r0 * 32 + h] = ua;
        sU[(r0 + 8) * 32 + h] = ub;
    }
    if (lt < 32) {
        float d = 0.0f;
#pragma unroll
        for (int cc = 0; cc < 32; cc++) d += sSAL[cc] * sW[4 * 1024 + cc * 32 + lt];
        sD[lt] = d;
    }
    __syncthreads();                           // E4

    // st GEMM (W2b, broadcast weights)
#pragma unroll
    for (int cc = 0; cc < 16; cc++) {
        float lo, hi;
        unpack2(st2[cc], lo, hi);
        gemm_row(y, pack2(lo), sW + 2 * 1024 + (2 * cc + 0) * 32);
        gemm_row(y, pack2(hi), sW + 2 * 1024 + (2 * cc + 1) * 32);
    }

    // finalize: add U/D/bias, relu, dot fc, reduce
    float loc = 0.0f;
    const ull* b2p = (const ull*)b2;
    const ull* fwp = (const ull*)fcw;
#pragma unroll
    for (int k = 0; k < 16; k++) {
        ull u = *(const ull*)(sU + i * 32 + 2 * k);
        ull v = addx2(y[k], addx2(u, b2p[k]));
        if (i == j) v = addx2(v, *(const ull*)(sD + 2 * k));
        float lo, hi;
        unpack2(v, lo, hi);
        float w0, w1;
        unpack2(fwp[k], w0, w1);
        loc += fmaxf(lo, 0.0f) * w0 + fmaxf(hi, 0.0f) * w1;
    }
#pragma unroll
    for (int o = 16; o > 0; o >>= 1) loc += __shfl_xor_sync(0xffffffffu, loc, o);
    if ((lt & 31) == 0) sRED[lt >> 5] = loc;
    __syncthreads();
    if (lt == 0) {
        float s = 0.0f;
#pragma unroll
        for (int w = 0; w < 8; w++) s += sRED[w];
        atomicAdd(&g_acc, s);
    }
    __syncthreads();
    if (tid == 0) {
        __threadfence();
        unsigned prev = atomicAdd(&g_done, 1);
        if (prev == GRID - 1) {
            float tot = atomicAdd(&g_acc, 0.0f);
            out[0] = tot + fcb[0];
            g_acc = 0.0f;
            g_done = 0;
            g_epoch = tgt;
            __threadfence();
        }
    }
}

extern "C" void kernel_launch(void* const* d_in, const int* in_sizes, int n_in,
                              void* d_out, int out_size) {
    const float* X   = (const float*)d_in[0];
    const int*   nbr = (const int*)d_in[1];
    const float* W1  = (const float*)d_in[2];
    const float* b1  = (const float*)d_in[3];
    const float* W2  = (const float*)d_in[4];
    const float* b2  = (const float*)d_in[5];
    const float* fcw = (const float*)d_in[6];
    const float* fcb = (const float*)d_in[7];
    float* out = (float*)d_out;

    cudaFuncSetAttribute(ccn_fused, cudaFuncAttributeMaxDynamicSharedMemorySize, SMEM_BYTES);
    ccn_fused<<<GRID, 512, SMEM_BYTES>>>(nbr, X, W1, b1, W2, b2, fcw, fcb, out);
}